// round 14
// baseline (speedup 1.0000x reference)
#include <cuda_runtime.h>
#include <cuda_fp16.h>
#include <cstdint>
#include <math.h>

#define MAXN 65536
#define MAXE (1 << 21)
#define DCOL 256

// ---------------- static device scratch ----------------
__device__ __half2 g_hw[MAXN * (DCOL / 2)];  // (h @ W) * dinv[row], fp16
__device__ __half g_z0[MAXN * DCOL];  // z0 / z2 (pre-BN), fp16
__device__ __half g_z1[MAXN * DCOL];  // z1 (pre-BN), fp16
__device__ int   g_deg[MAXN];         // starts 0; re-zeroed by k_agg each call
__device__ int   g_scan[MAXN];
__device__ int   g_rowptr[MAXN + 1];
__device__ int   g_cursor[MAXN];
__device__ int   g_csr[MAXE];
__device__ int   g_bsums[128];
__device__ float g_dinv[MAXN];
__device__ float g_colsum[DCOL];      // starts 0; zeroed by stats last-block
__device__ float g_colsq[DCOL];
__device__ int   g_stats_ctr;         // starts 0; reset by stats last-block
__device__ float g_sc[3][DCOL];
__device__ float g_sh[3][DCOL];
__device__ __half g_Wh[3][DCOL * DCOL];   // W fp16, transposed [n][k]

__device__ __forceinline__ float elu_act(float z, float sc, float sh) {
    float v = fmaf(z, sc, sh);
    return v > 0.f ? v : expm1f(v);
}

__device__ __forceinline__ void mma16816(float* d, const uint32_t* a, const uint32_t* b) {
    asm volatile(
        "mma.sync.aligned.m16n8k16.row.col.f32.f16.f16.f32 "
        "{%0,%1,%2,%3},{%4,%5,%6,%7},{%8,%9},{%0,%1,%2,%3};"
        : "+f"(d[0]), "+f"(d[1]), "+f"(d[2]), "+f"(d[3])
        : "r"(a[0]), "r"(a[1]), "r"(a[2]), "r"(a[3]), "r"(b[0]), "r"(b[1]));
}

__device__ __forceinline__ void ldsm_x4(uint32_t* r, uint32_t saddr) {
    asm volatile("ldmatrix.sync.aligned.m8n8.x4.shared.b16 {%0,%1,%2,%3}, [%4];"
                 : "=r"(r[0]), "=r"(r[1]), "=r"(r[2]), "=r"(r[3]) : "r"(saddr));
}

__device__ __forceinline__ void cp_async16(uint32_t saddr, const void* gptr) {
    asm volatile("cp.async.cg.shared.global [%0], [%1], 16;" :: "r"(saddr), "l"(gptr));
}

// accumulate 8 halves (packed in uint4) into float[8]
__device__ __forceinline__ void acc8(float* a, uint4 u) {
    __half2* h = (__half2*)&u;
    float2 f0 = __half22float2(h[0]);
    float2 f1 = __half22float2(h[1]);
    float2 f2 = __half22float2(h[2]);
    float2 f3 = __half22float2(h[3]);
    a[0] += f0.x; a[1] += f0.y; a[2] += f1.x; a[3] += f1.y;
    a[4] += f2.x; a[5] += f2.y; a[6] += f3.x; a[7] += f3.y;
}

// ---------------- preprocessing (5 launches) ----------------
__global__ void k_count_deg(const int* __restrict__ dst, int e) {
    int i = blockIdx.x * blockDim.x + threadIdx.x;
    if (i < e) atomicAdd(&g_deg[dst[i]], 1);
}

__global__ void k_scan_block(int n) {
    __shared__ int sh[1024];
    int i = blockIdx.x * 1024 + threadIdx.x;
    int v = 0;
    if (i < n) {
        v = g_deg[i] + 1;          // + self loop
        g_deg[i] = v;
        g_dinv[i] = rsqrtf((float)v);
    }
    sh[threadIdx.x] = v;
    __syncthreads();
    for (int off = 1; off < 1024; off <<= 1) {
        int t = (threadIdx.x >= off) ? sh[threadIdx.x - off] : 0;
        __syncthreads();
        sh[threadIdx.x] += t;
        __syncthreads();
    }
    if (i < n) g_scan[i] = sh[threadIdx.x];
    if (threadIdx.x == 1023) g_bsums[blockIdx.x] = sh[1023];
}

__global__ void k_scan_sums_prepW(int nb, const float* __restrict__ W0,
                                  const float* __restrict__ W1, const float* __restrict__ W2) {
    if (blockIdx.x == 0) {
        if (threadIdx.x == 0) {
            int acc = 0;
            for (int i = 0; i < nb; i++) { acc += g_bsums[i]; g_bsums[i] = acc; }
        }
        return;
    }
    int idx = (blockIdx.x - 1) * 256 + threadIdx.x;   // 0 .. 3*65536-1
    int layer = idx >> 16;
    int rem = idx & 65535;           // rem = k*256 + n
    int k = rem >> 8;
    int nn = rem & 255;
    const float* Ws = (layer == 0) ? W0 : (layer == 1) ? W1 : W2;
    g_Wh[layer][nn * 256 + k] = __float2half_rn(Ws[rem]);
}

__global__ void k_scan_final(int n) {
    int i = blockIdx.x * 1024 + threadIdx.x;
    if (i < n) {
        int off = (blockIdx.x > 0) ? g_bsums[blockIdx.x - 1] : 0;
        int incl = g_scan[i] + off;
        g_rowptr[i + 1] = incl;
        g_cursor[i] = incl - g_deg[i];
        if (i == 0) g_rowptr[0] = 0;
    }
}

__global__ void k_fill(const int* __restrict__ src, const int* __restrict__ dst, int e, int n) {
    int i = blockIdx.x * blockDim.x + threadIdx.x;
    if (i < e) {
        int d = dst[i];
        int p = atomicAdd(&g_cursor[d], 1);
        g_csr[p] = src[i];
    } else if (i - e < n) {
        int j = i - e;
        int p = atomicAdd(&g_cursor[j], 1);
        g_csr[p] = j;
    }
}

// ---------------- pipelined fp16 tensor-core GEMM ----------------
// Chw[r][c] = fp16( (act(A) @ W)[r][c] * dinv[r] ).
// MODE 0: A fp32 row-major, no activation (layer 0, A = x).
// MODE 1: A fp16 row-major (z), lazy BN+ELU applied via scl/sft.
// BM=64, BN=256, BK=32, 256 threads = 8 warps (2m x 4n), warp tile 32x64.
#define PADK 40
template <int MODE>
__global__ __launch_bounds__(256, 2)
void k_gemm(const void* __restrict__ Av,
            const __half* __restrict__ Wh,
            __half2* __restrict__ C, int M,
            const float* __restrict__ scl, const float* __restrict__ sft) {
    extern __shared__ __half sm[];
    __half* Ah = sm;                              // 2 stages * 64 * PADK
    __half* Bh = Ah + 2 * 64 * PADK;              // 2 stages * 256 * PADK

    uint32_t sAh = (uint32_t)__cvta_generic_to_shared(Ah);
    uint32_t sBh = (uint32_t)__cvta_generic_to_shared(Bh);

    int tid = threadIdx.x;
    int brow = blockIdx.x * 64;
    int lane = tid & 31;
    int warp = tid >> 5;
    int wm = warp & 1;
    int wn = warp >> 1;
    int g  = lane >> 2;
    int tg = lane & 3;

    int aRow = tid >> 2;
    int aCb  = (tid & 3) * 8;
    int gRow = brow + aRow;
    const float*  ApF = (const float*)Av  + (size_t)gRow * 256 + aCb;
    const __half* ApH = (const __half*)Av + (size_t)gRow * 256 + aCb;

    int bRow0 = tid >> 2;
    int bChunk = (tid & 3) * 8;

    int lmRow = lane & 15;
    int lmCol = (lane >> 4) * 8;

    float acc[2][8][4];
#pragma unroll
    for (int mt = 0; mt < 2; mt++)
#pragma unroll
        for (int nt = 0; nt < 8; nt++)
#pragma unroll
            for (int j = 0; j < 4; j++) acc[mt][nt][j] = 0.f;

    auto loadA = [&](int kt, float4& v0, float4& v1) {
        if (MODE == 0) {
            if (gRow < M) {
                v0 = *(const float4*)(ApF + kt);
                v1 = *(const float4*)(ApF + kt + 4);
            } else {
                v0 = make_float4(0.f, 0.f, 0.f, 0.f);
                v1 = make_float4(0.f, 0.f, 0.f, 0.f);
            }
        } else {
            uint4 u = make_uint4(0, 0, 0, 0);
            if (gRow < M) u = *(const uint4*)(ApH + kt);
            __half2* hp = (__half2*)&u;
            float2 f0 = __half22float2(hp[0]);
            float2 f1 = __half22float2(hp[1]);
            float2 f2 = __half22float2(hp[2]);
            float2 f3 = __half22float2(hp[3]);
            int c = kt + aCb;
            v0.x = elu_act(f0.x, scl[c + 0], sft[c + 0]);
            v0.y = elu_act(f0.y, scl[c + 1], sft[c + 1]);
            v0.z = elu_act(f1.x, scl[c + 2], sft[c + 2]);
            v0.w = elu_act(f1.y, scl[c + 3], sft[c + 3]);
            v1.x = elu_act(f2.x, scl[c + 4], sft[c + 4]);
            v1.y = elu_act(f2.y, scl[c + 5], sft[c + 5]);
            v1.z = elu_act(f3.x, scl[c + 6], sft[c + 6]);
            v1.w = elu_act(f3.y, scl[c + 7], sft[c + 7]);
        }
    };
    auto storeA = [&](int stage, float4 v0, float4 v1) {
        __half* ah = Ah + stage * 64 * PADK + aRow * PADK + aCb;
        *(__half2*)(ah + 0) = __floats2half2_rn(v0.x, v0.y);
        *(__half2*)(ah + 2) = __floats2half2_rn(v0.z, v0.w);
        *(__half2*)(ah + 4) = __floats2half2_rn(v1.x, v1.y);
        *(__half2*)(ah + 6) = __floats2half2_rn(v1.z, v1.w);
    };
    auto asyncB = [&](int stage, int kt) {
#pragma unroll
        for (int rep = 0; rep < 4; rep++) {
            int row = bRow0 + rep * 64;
            uint32_t soff = (uint32_t)((stage * 256 + row) * PADK + bChunk) * 2;
            const __half* gh = Wh + (size_t)row * 256 + kt + bChunk;
            cp_async16(sBh + soff, gh);
        }
    };
    auto compute = [&](int stage) {
#pragma unroll
        for (int ks = 0; ks < 2; ks++) {
            int k0 = ks * 16;
            uint32_t ah[2][4];
#pragma unroll
            for (int mt = 0; mt < 2; mt++) {
                int m = wm * 32 + mt * 16 + lmRow;
                uint32_t off = (uint32_t)((stage * 64 + m) * PADK + k0 + lmCol) * 2;
                ldsm_x4(ah[mt], sAh + off);
            }
#pragma unroll
            for (int pair = 0; pair < 4; pair++) {
                int n0 = wn * 64 + pair * 16 + lmRow;
                uint32_t off = (uint32_t)((stage * 256 + n0) * PADK + k0 + lmCol) * 2;
                uint32_t bhr[4];
                ldsm_x4(bhr, sBh + off);
                uint32_t b_ev[2] = {bhr[0], bhr[2]};
                uint32_t b_od[2] = {bhr[1], bhr[3]};
                int nt0 = pair * 2;
#pragma unroll
                for (int mt = 0; mt < 2; mt++) {
                    mma16816(acc[mt][nt0], ah[mt], b_ev);
                    mma16816(acc[mt][nt0 + 1], ah[mt], b_od);
                }
            }
        }
    };

    {
        asyncB(0, 0);
        float4 v0, v1;
        loadA(0, v0, v1);
        storeA(0, v0, v1);
        asm volatile("cp.async.commit_group;");
        asm volatile("cp.async.wait_group 0;");
        __syncthreads();
    }

#pragma unroll
    for (int it = 0; it < 8; ++it) {
        int cur = it & 1;
        float4 v0, v1;
        if (it < 7) {
            asyncB(cur ^ 1, (it + 1) * 32);
            loadA((it + 1) * 32, v0, v1);
        }
        asm volatile("cp.async.commit_group;");
        compute(cur);
        if (it < 7) storeA(cur ^ 1, v0, v1);
        asm volatile("cp.async.wait_group 0;");
        __syncthreads();
    }

#pragma unroll
    for (int mt = 0; mt < 2; mt++) {
        int r0 = brow + wm * 32 + mt * 16 + g;
        int r1 = r0 + 8;
        float s0 = (r0 < M) ? g_dinv[r0] : 0.f;
        float s1 = (r1 < M) ? g_dinv[r1] : 0.f;
#pragma unroll
        for (int nt = 0; nt < 8; nt++) {
            int col = wn * 64 + nt * 8 + tg * 2;
            if (r0 < M)
                C[(size_t)r0 * 128 + (col >> 1)] =
                    __floats2half2_rn(acc[mt][nt][0] * s0, acc[mt][nt][1] * s0);
            if (r1 < M)
                C[(size_t)r1 * 128 + (col >> 1)] =
                    __floats2half2_rn(acc[mt][nt][2] * s1, acc[mt][nt][3] * s1);
        }
    }
}

// ---------------- aggregation: 8 rows/block, 32 lanes x 16B per row ----------------
// z[d] = act_or_raw(prev[d]) + dinv[d]*sum_s hw16[s] + bias
// Each lane owns 8 halves (one uint4 load per edge). 8-way edge unroll (MLP=8).
__global__ void k_agg(const uint4* __restrict__ hws,   // row stride 32 uint4
                      const float4* __restrict__ prev_f, const __half* __restrict__ prev_h,
                      const float* __restrict__ pscl, const float* __restrict__ psft,
                      const float4* __restrict__ bias, uint4* __restrict__ z, int n) {
    int row = blockIdx.x * 8 + (threadIdx.x >> 5);
    if (row >= n) return;
    int lane = threadIdx.x & 31;
    if (lane == 0) g_deg[row] = 0;   // reset for next graph replay
    int s0 = g_rowptr[row], s1 = g_rowptr[row + 1];

    float a0[8] = {0.f, 0.f, 0.f, 0.f, 0.f, 0.f, 0.f, 0.f};
    float a1[8] = {0.f, 0.f, 0.f, 0.f, 0.f, 0.f, 0.f, 0.f};
    float a2[8] = {0.f, 0.f, 0.f, 0.f, 0.f, 0.f, 0.f, 0.f};
    float a3[8] = {0.f, 0.f, 0.f, 0.f, 0.f, 0.f, 0.f, 0.f};

    int e = s0;
    // 8-way unrolled gather: 8 independent 16B loads in flight
    for (; e + 7 < s1; e += 8) {
        int i0 = g_csr[e + 0];
        int i1 = g_csr[e + 1];
        int i2 = g_csr[e + 2];
        int i3 = g_csr[e + 3];
        int i4 = g_csr[e + 4];
        int i5 = g_csr[e + 5];
        int i6 = g_csr[e + 6];
        int i7 = g_csr[e + 7];
        uint4 u0 = hws[(size_t)i0 * 32 + lane];
        uint4 u1 = hws[(size_t)i1 * 32 + lane];
        uint4 u2 = hws[(size_t)i2 * 32 + lane];
        uint4 u3 = hws[(size_t)i3 * 32 + lane];
        uint4 u4 = hws[(size_t)i4 * 32 + lane];
        uint4 u5 = hws[(size_t)i5 * 32 + lane];
        uint4 u6 = hws[(size_t)i6 * 32 + lane];
        uint4 u7 = hws[(size_t)i7 * 32 + lane];
        acc8(a0, u0);
        acc8(a1, u1);
        acc8(a2, u2);
        acc8(a3, u3);
        acc8(a0, u4);
        acc8(a1, u5);
        acc8(a2, u6);
        acc8(a3, u7);
    }
    for (; e + 3 < s1; e += 4) {
        int i0 = g_csr[e + 0];
        int i1 = g_csr[e + 1];
        int i2 = g_csr[e + 2];
        int i3 = g_csr[e + 3];
        uint4 u0 = hws[(size_t)i0 * 32 + lane];
        uint4 u1 = hws[(size_t)i1 * 32 + lane];
        uint4 u2 = hws[(size_t)i2 * 32 + lane];
        uint4 u3 = hws[(size_t)i3 * 32 + lane];
        acc8(a0, u0);
        acc8(a1, u1);
        acc8(a2, u2);
        acc8(a3, u3);
    }
    for (; e < s1; ++e) {
        int i0 = g_csr[e];
        acc8(a0, hws[(size_t)i0 * 32 + lane]);
    }
#pragma unroll
    for (int j = 0; j < 8; j++) a0[j] += (a1[j] + a2[j]) + a3[j];

    float d = g_dinv[row];
    float4 b0 = bias[lane * 2];
    float4 b1 = bias[lane * 2 + 1];
    float o[8];
    o[0] = fmaf(d, a0[0], b0.x);
    o[1] = fmaf(d, a0[1], b0.y);
    o[2] = fmaf(d, a0[2], b0.z);
    o[3] = fmaf(d, a0[3], b0.w);
    o[4] = fmaf(d, a0[4], b1.x);
    o[5] = fmaf(d, a0[5], b1.y);
    o[6] = fmaf(d, a0[6], b1.z);
    o[7] = fmaf(d, a0[7], b1.w);

    if (prev_f) {
        float4 p0 = prev_f[(size_t)row * 64 + lane * 2];
        float4 p1 = prev_f[(size_t)row * 64 + lane * 2 + 1];
        o[0] += p0.x; o[1] += p0.y; o[2] += p0.z; o[3] += p0.w;
        o[4] += p1.x; o[5] += p1.y; o[6] += p1.z; o[7] += p1.w;
    } else if (prev_h) {
        uint4 ph = ((const uint4*)prev_h)[(size_t)row * 32 + lane];
        __half2* hp = (__half2*)&ph;
        float pf[8];
        float2 f0 = __half22float2(hp[0]);
        float2 f1 = __half22float2(hp[1]);
        float2 f2 = __half22float2(hp[2]);
        float2 f3 = __half22float2(hp[3]);
        pf[0] = f0.x; pf[1] = f0.y; pf[2] = f1.x; pf[3] = f1.y;
        pf[4] = f2.x; pf[5] = f2.y; pf[6] = f3.x; pf[7] = f3.y;
        int c = lane * 8;
#pragma unroll
        for (int j = 0; j < 8; j++) o[j] += elu_act(pf[j], pscl[c + j], psft[c + j]);
    }

    __half2 h0 = __floats2half2_rn(o[0], o[1]);
    __half2 h1 = __floats2half2_rn(o[2], o[3]);
    __half2 h2 = __floats2half2_rn(o[4], o[5]);
    __half2 h3 = __floats2half2_rn(o[6], o[7]);
    uint4 pk;
    pk.x = *(uint32_t*)&h0;
    pk.y = *(uint32_t*)&h1;
    pk.z = *(uint32_t*)&h2;
    pk.w = *(uint32_t*)&h3;
    z[(size_t)row * 32 + lane] = pk;
}

// ---------------- batchnorm stats + fused finalize (last-block) ----------------
__global__ void k_stats(const __half* __restrict__ z,
                        const float* __restrict__ gamma, const float* __restrict__ beta,
                        int n, int layer) {
    int t = threadIdx.x;
    int r0 = blockIdx.x * 128;
    int r1 = min(n, r0 + 128);
    float s = 0.f, q = 0.f;
    for (int r = r0; r < r1; ++r) {
        float v = __half2float(z[(size_t)r * DCOL + t]);
        s += v;
        q += v * v;
    }
    atomicAdd(&g_colsum[t], s);
    atomicAdd(&g_colsq[t], q);
    __threadfence();

    __shared__ int last;
    if (t == 0) last = (atomicAdd(&g_stats_ctr, 1) == (int)gridDim.x - 1) ? 1 : 0;
    __syncthreads();
    if (last) {
        float inv_n = 1.f / (float)n;
        float mu = g_colsum[t] * inv_n;
        float var = g_colsq[t] * inv_n - mu * mu;
        float rs = rsqrtf(var + 1e-5f);
        float sc = gamma[t] * rs;
        g_sc[layer][t] = sc;
        g_sh[layer][t] = beta[t] - mu * sc;
        g_colsum[t] = 0.f;
        g_colsq[t] = 0.f;
        if (t == 0) g_stats_ctr = 0;
    }
}

// ---------------- pool + readout (lazy act on z2, fp16) ----------------
__global__ void k_pool_out(const __half* __restrict__ z, const int* __restrict__ batch,
                           const float* __restrict__ Wr, const float* __restrict__ br,
                           float* __restrict__ out, int n) {
    int gg = blockIdx.x;
    int t = threadIdx.x;
    int lo = 0, hi = n;
    while (lo < hi) { int m = (lo + hi) >> 1; if (batch[m] < gg) lo = m + 1; else hi = m; }
    int start = lo;
    lo = start; hi = n;
    while (lo < hi) { int m = (lo + hi) >> 1; if (batch[m] < gg + 1) lo = m + 1; else hi = m; }
    int end = lo;

    float sc = g_sc[2][t], sh = g_sh[2][t];
    float sum = 0.f;
    for (int r = start; r < end; ++r)
        sum += elu_act(__half2float(z[(size_t)r * DCOL + t]), sc, sh);
    float cnt = (float)(end - start);
    float v = sum / fmaxf(cnt, 1.f);

    __shared__ float red[DCOL];
    for (int c = 0; c < 2; ++c) {
        red[t] = v * Wr[t * 2 + c];
        __syncthreads();
        for (int s = 128; s > 0; s >>= 1) {
            if (t < s) red[t] += red[t + s];
            __syncthreads();
        }
        if (t == 0) out[gg * 2 + c] = red[0] + br[c];
        __syncthreads();
    }
}

// ---------------- launch ----------------
extern "C" void kernel_launch(void* const* d_in, const int* in_sizes, int n_in,
                              void* d_out, int out_size) {
    const float* x     = (const float*)d_in[0];
    const int*   ei    = (const int*)d_in[1];
    const int*   batch = (const int*)d_in[2];
    const float* W[3]     = { (const float*)d_in[3],  (const float*)d_in[7],  (const float*)d_in[11] };
    const float* b[3]     = { (const float*)d_in[4],  (const float*)d_in[8],  (const float*)d_in[12] };
    const float* gamma[3] = { (const float*)d_in[5],  (const float*)d_in[9],  (const float*)d_in[13] };
    const float* beta[3]  = { (const float*)d_in[6],  (const float*)d_in[10], (const float*)d_in[14] };
    const float* Wr = (const float*)d_in[15];
    const float* br = (const float*)d_in[16];
    float* out = (float*)d_out;

    int n = in_sizes[0] / DCOL;
    int e = in_sizes[1] / 2;
    int g = out_size / 2;
    const int* src = ei;
    const int* dst = ei + e;

    __half2* p_hw;
    __half *p_z0, *p_z1, *p_wh;
    float *p_sc, *p_sh;
    cudaGetSymbolAddress((void**)&p_hw, g_hw);
    cudaGetSymbolAddress((void**)&p_z0, g_z0);
    cudaGetSymbolAddress((void**)&p_z1, g_z1);
    cudaGetSymbolAddress((void**)&p_sc, g_sc);
    cudaGetSymbolAddress((void**)&p_sh, g_sh);
    cudaGetSymbolAddress((void**)&p_wh, g_Wh);

    const int GEMM_SMEM = (2 * 64 * PADK + 2 * 256 * PADK) * 2;
    cudaFuncSetAttribute(k_gemm<0>, cudaFuncAttributeMaxDynamicSharedMemorySize, GEMM_SMEM);
    cudaFuncSetAttribute(k_gemm<1>, cudaFuncAttributeMaxDynamicSharedMemorySize, GEMM_SMEM);

    // ---- preprocessing: 5 launches, single stream ----
    int nb256_e = (e + 255) / 256;
    int nb1024  = (n + 1023) / 1024;
    int nb_fill = (e + n + 255) / 256;

    k_count_deg<<<nb256_e, 256>>>(dst, e);
    k_scan_block<<<nb1024, 1024>>>(n);
    k_scan_sums_prepW<<<1 + 768, 256>>>(nb1024, W[0], W[1], W[2]);
    k_scan_final<<<nb1024, 1024>>>(n);
    k_fill<<<nb_fill, 256>>>(src, dst, e, n);

    int gemm_grid = (n + 63) / 64;
    int nb_agg   = (n + 7) / 8;
    int nb_stats = (n + 127) / 128;

    // ---- layer 0: A=x raw (fp32), prev=none -> z0 ----
    k_gemm<0><<<gemm_grid, 256, GEMM_SMEM>>>(x, p_wh + 0 * 65536, p_hw, n, nullptr, nullptr);
    k_agg<<<nb_agg, 256>>>((const uint4*)p_hw, nullptr, nullptr, nullptr, nullptr,
                           (const float4*)b[0], (uint4*)p_z0, n);
    k_stats<<<nb_stats, 256>>>(p_z0, gamma[0], beta[0], n, 0);

    // ---- layer 1: A=act0(z0) fp16, prev=x fp32 -> z1 ----
    k_gemm<1><<<gemm_grid, 256, GEMM_SMEM>>>(p_z0, p_wh + 1 * 65536, p_hw, n,
                                             p_sc + 0 * DCOL, p_sh + 0 * DCOL);
    k_agg<<<nb_agg, 256>>>((const uint4*)p_hw, (const float4*)x, nullptr, nullptr, nullptr,
                           (const float4*)b[1], (uint4*)p_z1, n);
    k_stats<<<nb_stats, 256>>>(p_z1, gamma[1], beta[1], n, 1);

    // ---- layer 2: A=act1(z1) fp16, prev=act0(z0) fp16 -> z2 (overwrites z0) ----
    k_gemm<1><<<gemm_grid, 256, GEMM_SMEM>>>(p_z1, p_wh + 2 * 65536, p_hw, n,
                                             p_sc + 1 * DCOL, p_sh + 1 * DCOL);
    k_agg<<<nb_agg, 256>>>((const uint4*)p_hw, nullptr, p_z0,
                           p_sc + 0 * DCOL, p_sh + 0 * DCOL,
                           (const float4*)b[2], (uint4*)p_z0, n);
    k_stats<<<nb_stats, 256>>>(p_z0, gamma[2], beta[2], n, 2);

    // ---- pool + readout (act2 lazy) ----
    k_pool_out<<<g, 256>>>(p_z0, batch, Wr, br, out, n);
}

// round 15
// speedup vs baseline: 1.0617x; 1.0617x over previous
#include <cuda_runtime.h>
#include <cuda_fp16.h>
#include <cstdint>
#include <math.h>

#define MAXN 65536
#define MAXE (1 << 21)
#define DCOL 256

// ---------------- static device scratch ----------------
__device__ __half2 g_hw[MAXN * (DCOL / 2)];  // (h @ W) * dinv[row], fp16
__device__ __half g_z0[MAXN * DCOL];  // z0 / z2 (pre-BN), fp16
__device__ __half g_z1[MAXN * DCOL];  // z1 (pre-BN), fp16
__device__ int   g_deg[MAXN];         // starts 0; re-zeroed by k_agg each call
__device__ int   g_scan[MAXN];
__device__ int   g_rowptr[MAXN + 1];
__device__ int   g_cursor[MAXN];
__device__ int   g_csr[MAXE];
__device__ int   g_bsums[128];
__device__ float g_dinv[MAXN];
__device__ float g_colsum[DCOL];      // starts 0; zeroed by stats last-block
__device__ float g_colsq[DCOL];
__device__ int   g_stats_ctr;         // starts 0; reset by stats last-block
__device__ float g_sc[3][DCOL];
__device__ float g_sh[3][DCOL];
__device__ __half g_Wh[3][DCOL * DCOL];   // W fp16, transposed [n][k]

__device__ __forceinline__ float elu_act(float z, float sc, float sh) {
    float v = fmaf(z, sc, sh);
    return v > 0.f ? v : expm1f(v);
}

__device__ __forceinline__ void mma16816(float* d, const uint32_t* a, const uint32_t* b) {
    asm volatile(
        "mma.sync.aligned.m16n8k16.row.col.f32.f16.f16.f32 "
        "{%0,%1,%2,%3},{%4,%5,%6,%7},{%8,%9},{%0,%1,%2,%3};"
        : "+f"(d[0]), "+f"(d[1]), "+f"(d[2]), "+f"(d[3])
        : "r"(a[0]), "r"(a[1]), "r"(a[2]), "r"(a[3]), "r"(b[0]), "r"(b[1]));
}

__device__ __forceinline__ void ldsm_x4(uint32_t* r, uint32_t saddr) {
    asm volatile("ldmatrix.sync.aligned.m8n8.x4.shared.b16 {%0,%1,%2,%3}, [%4];"
                 : "=r"(r[0]), "=r"(r[1]), "=r"(r[2]), "=r"(r[3]) : "r"(saddr));
}

__device__ __forceinline__ void cp_async16(uint32_t saddr, const void* gptr) {
    asm volatile("cp.async.cg.shared.global [%0], [%1], 16;" :: "r"(saddr), "l"(gptr));
}

// accumulate 8 halves (packed in uint4) into float[8]
__device__ __forceinline__ void acc8(float* a, uint4 u) {
    __half2* h = (__half2*)&u;
    float2 f0 = __half22float2(h[0]);
    float2 f1 = __half22float2(h[1]);
    float2 f2 = __half22float2(h[2]);
    float2 f3 = __half22float2(h[3]);
    a[0] += f0.x; a[1] += f0.y; a[2] += f1.x; a[3] += f1.y;
    a[4] += f2.x; a[5] += f2.y; a[6] += f3.x; a[7] += f3.y;
}

// ---------------- preprocessing (5 launches) ----------------
__global__ void k_count_deg(const int* __restrict__ dst, int e) {
    int i = blockIdx.x * blockDim.x + threadIdx.x;
    if (i < e) atomicAdd(&g_deg[dst[i]], 1);
}

__global__ void k_scan_block(int n) {
    __shared__ int sh[1024];
    int i = blockIdx.x * 1024 + threadIdx.x;
    int v = 0;
    if (i < n) {
        v = g_deg[i] + 1;          // + self loop
        g_deg[i] = v;
        g_dinv[i] = rsqrtf((float)v);
    }
    sh[threadIdx.x] = v;
    __syncthreads();
    for (int off = 1; off < 1024; off <<= 1) {
        int t = (threadIdx.x >= off) ? sh[threadIdx.x - off] : 0;
        __syncthreads();
        sh[threadIdx.x] += t;
        __syncthreads();
    }
    if (i < n) g_scan[i] = sh[threadIdx.x];
    if (threadIdx.x == 1023) g_bsums[blockIdx.x] = sh[1023];
}

__global__ void k_scan_sums_prepW(int nb, const float* __restrict__ W0,
                                  const float* __restrict__ W1, const float* __restrict__ W2) {
    if (blockIdx.x == 0) {
        if (threadIdx.x == 0) {
            int acc = 0;
            for (int i = 0; i < nb; i++) { acc += g_bsums[i]; g_bsums[i] = acc; }
        }
        return;
    }
    int idx = (blockIdx.x - 1) * 256 + threadIdx.x;   // 0 .. 3*65536-1
    int layer = idx >> 16;
    int rem = idx & 65535;           // rem = k*256 + n
    int k = rem >> 8;
    int nn = rem & 255;
    const float* Ws = (layer == 0) ? W0 : (layer == 1) ? W1 : W2;
    g_Wh[layer][nn * 256 + k] = __float2half_rn(Ws[rem]);
}

__global__ void k_scan_final(int n) {
    int i = blockIdx.x * 1024 + threadIdx.x;
    if (i < n) {
        int off = (blockIdx.x > 0) ? g_bsums[blockIdx.x - 1] : 0;
        int incl = g_scan[i] + off;
        g_rowptr[i + 1] = incl;
        g_cursor[i] = incl - g_deg[i];
        if (i == 0) g_rowptr[0] = 0;
    }
}

__global__ void k_fill(const int* __restrict__ src, const int* __restrict__ dst, int e, int n) {
    int i = blockIdx.x * blockDim.x + threadIdx.x;
    if (i < e) {
        int d = dst[i];
        int p = atomicAdd(&g_cursor[d], 1);
        g_csr[p] = src[i];
    } else if (i - e < n) {
        int j = i - e;
        int p = atomicAdd(&g_cursor[j], 1);
        g_csr[p] = j;
    }
}

// ---------------- pipelined fp16 tensor-core GEMM ----------------
// Chw[r][c] = fp16( (act(A) @ W)[r][c] * dinv[r] ).
// MODE 0: A fp32 row-major, no activation (layer 0, A = x).
// MODE 1: A fp16 row-major (z), lazy BN+ELU applied via scl/sft.
// BM=64, BN=256, BK=32, 256 threads = 8 warps (2m x 4n), warp tile 32x64.
#define PADK 40
template <int MODE>
__global__ __launch_bounds__(256, 2)
void k_gemm(const void* __restrict__ Av,
            const __half* __restrict__ Wh,
            __half2* __restrict__ C, int M,
            const float* __restrict__ scl, const float* __restrict__ sft) {
    extern __shared__ __half sm[];
    __half* Ah = sm;                              // 2 stages * 64 * PADK
    __half* Bh = Ah + 2 * 64 * PADK;              // 2 stages * 256 * PADK

    uint32_t sAh = (uint32_t)__cvta_generic_to_shared(Ah);
    uint32_t sBh = (uint32_t)__cvta_generic_to_shared(Bh);

    int tid = threadIdx.x;
    int brow = blockIdx.x * 64;
    int lane = tid & 31;
    int warp = tid >> 5;
    int wm = warp & 1;
    int wn = warp >> 1;
    int g  = lane >> 2;
    int tg = lane & 3;

    int aRow = tid >> 2;
    int aCb  = (tid & 3) * 8;
    int gRow = brow + aRow;
    const float*  ApF = (const float*)Av  + (size_t)gRow * 256 + aCb;
    const __half* ApH = (const __half*)Av + (size_t)gRow * 256 + aCb;

    int bRow0 = tid >> 2;
    int bChunk = (tid & 3) * 8;

    int lmRow = lane & 15;
    int lmCol = (lane >> 4) * 8;

    float acc[2][8][4];
#pragma unroll
    for (int mt = 0; mt < 2; mt++)
#pragma unroll
        for (int nt = 0; nt < 8; nt++)
#pragma unroll
            for (int j = 0; j < 4; j++) acc[mt][nt][j] = 0.f;

    auto loadA = [&](int kt, float4& v0, float4& v1) {
        if (MODE == 0) {
            if (gRow < M) {
                v0 = *(const float4*)(ApF + kt);
                v1 = *(const float4*)(ApF + kt + 4);
            } else {
                v0 = make_float4(0.f, 0.f, 0.f, 0.f);
                v1 = make_float4(0.f, 0.f, 0.f, 0.f);
            }
        } else {
            uint4 u = make_uint4(0, 0, 0, 0);
            if (gRow < M) u = *(const uint4*)(ApH + kt);
            __half2* hp = (__half2*)&u;
            float2 f0 = __half22float2(hp[0]);
            float2 f1 = __half22float2(hp[1]);
            float2 f2 = __half22float2(hp[2]);
            float2 f3 = __half22float2(hp[3]);
            int c = kt + aCb;
            v0.x = elu_act(f0.x, scl[c + 0], sft[c + 0]);
            v0.y = elu_act(f0.y, scl[c + 1], sft[c + 1]);
            v0.z = elu_act(f1.x, scl[c + 2], sft[c + 2]);
            v0.w = elu_act(f1.y, scl[c + 3], sft[c + 3]);
            v1.x = elu_act(f2.x, scl[c + 4], sft[c + 4]);
            v1.y = elu_act(f2.y, scl[c + 5], sft[c + 5]);
            v1.z = elu_act(f3.x, scl[c + 6], sft[c + 6]);
            v1.w = elu_act(f3.y, scl[c + 7], sft[c + 7]);
        }
    };
    auto storeA = [&](int stage, float4 v0, float4 v1) {
        __half* ah = Ah + stage * 64 * PADK + aRow * PADK + aCb;
        *(__half2*)(ah + 0) = __floats2half2_rn(v0.x, v0.y);
        *(__half2*)(ah + 2) = __floats2half2_rn(v0.z, v0.w);
        *(__half2*)(ah + 4) = __floats2half2_rn(v1.x, v1.y);
        *(__half2*)(ah + 6) = __floats2half2_rn(v1.z, v1.w);
    };
    auto asyncB = [&](int stage, int kt) {
#pragma unroll
        for (int rep = 0; rep < 4; rep++) {
            int row = bRow0 + rep * 64;
            uint32_t soff = (uint32_t)((stage * 256 + row) * PADK + bChunk) * 2;
            const __half* gh = Wh + (size_t)row * 256 + kt + bChunk;
            cp_async16(sBh + soff, gh);
        }
    };
    auto compute = [&](int stage) {
#pragma unroll
        for (int ks = 0; ks < 2; ks++) {
            int k0 = ks * 16;
            uint32_t ah[2][4];
#pragma unroll
            for (int mt = 0; mt < 2; mt++) {
                int m = wm * 32 + mt * 16 + lmRow;
                uint32_t off = (uint32_t)((stage * 64 + m) * PADK + k0 + lmCol) * 2;
                ldsm_x4(ah[mt], sAh + off);
            }
#pragma unroll
            for (int pair = 0; pair < 4; pair++) {
                int n0 = wn * 64 + pair * 16 + lmRow;
                uint32_t off = (uint32_t)((stage * 256 + n0) * PADK + k0 + lmCol) * 2;
                uint32_t bhr[4];
                ldsm_x4(bhr, sBh + off);
                uint32_t b_ev[2] = {bhr[0], bhr[2]};
                uint32_t b_od[2] = {bhr[1], bhr[3]};
                int nt0 = pair * 2;
#pragma unroll
                for (int mt = 0; mt < 2; mt++) {
                    mma16816(acc[mt][nt0], ah[mt], b_ev);
                    mma16816(acc[mt][nt0 + 1], ah[mt], b_od);
                }
            }
        }
    };

    {
        asyncB(0, 0);
        float4 v0, v1;
        loadA(0, v0, v1);
        storeA(0, v0, v1);
        asm volatile("cp.async.commit_group;");
        asm volatile("cp.async.wait_group 0;");
        __syncthreads();
    }

#pragma unroll
    for (int it = 0; it < 8; ++it) {
        int cur = it & 1;
        float4 v0, v1;
        if (it < 7) {
            asyncB(cur ^ 1, (it + 1) * 32);
            loadA((it + 1) * 32, v0, v1);
        }
        asm volatile("cp.async.commit_group;");
        compute(cur);
        if (it < 7) storeA(cur ^ 1, v0, v1);
        asm volatile("cp.async.wait_group 0;");
        __syncthreads();
    }

#pragma unroll
    for (int mt = 0; mt < 2; mt++) {
        int r0 = brow + wm * 32 + mt * 16 + g;
        int r1 = r0 + 8;
        float s0 = (r0 < M) ? g_dinv[r0] : 0.f;
        float s1 = (r1 < M) ? g_dinv[r1] : 0.f;
#pragma unroll
        for (int nt = 0; nt < 8; nt++) {
            int col = wn * 64 + nt * 8 + tg * 2;
            if (r0 < M)
                C[(size_t)r0 * 128 + (col >> 1)] =
                    __floats2half2_rn(acc[mt][nt][0] * s0, acc[mt][nt][1] * s0);
            if (r1 < M)
                C[(size_t)r1 * 128 + (col >> 1)] =
                    __floats2half2_rn(acc[mt][nt][2] * s1, acc[mt][nt][3] * s1);
        }
    }
}

// ---------------- aggregation: 8 rows/block, 32 lanes x 16B per row (R13) ----------------
// z[d] = act_or_raw(prev[d]) + dinv[d]*sum_s hw16[s] + bias
// Each lane owns 8 halves (one uint4 load per edge). 4-way edge unroll.
__global__ void k_agg(const uint4* __restrict__ hws,   // row stride 32 uint4
                      const float4* __restrict__ prev_f, const __half* __restrict__ prev_h,
                      const float* __restrict__ pscl, const float* __restrict__ psft,
                      const float4* __restrict__ bias, uint4* __restrict__ z, int n) {
    int row = blockIdx.x * 8 + (threadIdx.x >> 5);
    if (row >= n) return;
    int lane = threadIdx.x & 31;
    if (lane == 0) g_deg[row] = 0;   // reset for next graph replay
    int s0 = g_rowptr[row], s1 = g_rowptr[row + 1];

    float a0[8] = {0.f, 0.f, 0.f, 0.f, 0.f, 0.f, 0.f, 0.f};
    float a1[8] = {0.f, 0.f, 0.f, 0.f, 0.f, 0.f, 0.f, 0.f};

    int e = s0;
    for (; e + 3 < s1; e += 4) {
        int sa = g_csr[e + 0];
        int sb = g_csr[e + 1];
        int sc = g_csr[e + 2];
        int sd = g_csr[e + 3];
        uint4 ua = hws[(size_t)sa * 32 + lane];
        uint4 ub = hws[(size_t)sb * 32 + lane];
        uint4 uc = hws[(size_t)sc * 32 + lane];
        uint4 ud = hws[(size_t)sd * 32 + lane];
        acc8(a0, ua);
        acc8(a1, ub);
        acc8(a0, uc);
        acc8(a1, ud);
    }
    for (; e < s1; ++e) {
        int sa = g_csr[e];
        acc8(a0, hws[(size_t)sa * 32 + lane]);
    }
#pragma unroll
    for (int j = 0; j < 8; j++) a0[j] += a1[j];

    float d = g_dinv[row];
    float4 b0 = bias[lane * 2];
    float4 b1 = bias[lane * 2 + 1];
    float o[8];
    o[0] = fmaf(d, a0[0], b0.x);
    o[1] = fmaf(d, a0[1], b0.y);
    o[2] = fmaf(d, a0[2], b0.z);
    o[3] = fmaf(d, a0[3], b0.w);
    o[4] = fmaf(d, a0[4], b1.x);
    o[5] = fmaf(d, a0[5], b1.y);
    o[6] = fmaf(d, a0[6], b1.z);
    o[7] = fmaf(d, a0[7], b1.w);

    if (prev_f) {
        float4 p0 = prev_f[(size_t)row * 64 + lane * 2];
        float4 p1 = prev_f[(size_t)row * 64 + lane * 2 + 1];
        o[0] += p0.x; o[1] += p0.y; o[2] += p0.z; o[3] += p0.w;
        o[4] += p1.x; o[5] += p1.y; o[6] += p1.z; o[7] += p1.w;
    } else if (prev_h) {
        uint4 ph = ((const uint4*)prev_h)[(size_t)row * 32 + lane];
        __half2* hp = (__half2*)&ph;
        float pf[8];
        float2 f0 = __half22float2(hp[0]);
        float2 f1 = __half22float2(hp[1]);
        float2 f2 = __half22float2(hp[2]);
        float2 f3 = __half22float2(hp[3]);
        pf[0] = f0.x; pf[1] = f0.y; pf[2] = f1.x; pf[3] = f1.y;
        pf[4] = f2.x; pf[5] = f2.y; pf[6] = f3.x; pf[7] = f3.y;
        int c = lane * 8;
#pragma unroll
        for (int j = 0; j < 8; j++) o[j] += elu_act(pf[j], pscl[c + j], psft[c + j]);
    }

    __half2 h0 = __floats2half2_rn(o[0], o[1]);
    __half2 h1 = __floats2half2_rn(o[2], o[3]);
    __half2 h2 = __floats2half2_rn(o[4], o[5]);
    __half2 h3 = __floats2half2_rn(o[6], o[7]);
    uint4 pk;
    pk.x = *(uint32_t*)&h0;
    pk.y = *(uint32_t*)&h1;
    pk.z = *(uint32_t*)&h2;
    pk.w = *(uint32_t*)&h3;
    z[(size_t)row * 32 + lane] = pk;
}

// ---------------- batchnorm stats (vectorized uint4 reads) + fused finalize ----------------
// 256 threads = 32 lanes x 8 row-groups. Each thread reads uint4 (8 fp16 cols)
// for 16 rows (its row-group), accumulates s[8]/q[8], smem-reduces over the
// 8 row-groups, then 2 atomics per column (391 blocks -> cheap).
__global__ void k_stats(const __half* __restrict__ z,
                        const float* __restrict__ gamma, const float* __restrict__ beta,
                        int n, int layer) {
    int t = threadIdx.x;
    int lane = t & 31;      // column group: cols lane*8 .. lane*8+7
    int rg = t >> 5;        // row-group 0..7
    int r0 = blockIdx.x * 128;

    float s[8] = {0.f, 0.f, 0.f, 0.f, 0.f, 0.f, 0.f, 0.f};
    float q[8] = {0.f, 0.f, 0.f, 0.f, 0.f, 0.f, 0.f, 0.f};

    const uint4* z4 = (const uint4*)z;   // row stride 32 uint4
    for (int r = r0 + rg; r < min(n, r0 + 128); r += 8) {
        uint4 u = z4[(size_t)r * 32 + lane];
        __half2* h = (__half2*)&u;
        float2 f0 = __half22float2(h[0]);
        float2 f1 = __half22float2(h[1]);
        float2 f2 = __half22float2(h[2]);
        float2 f3 = __half22float2(h[3]);
        s[0] += f0.x; q[0] += f0.x * f0.x;
        s[1] += f0.y; q[1] += f0.y * f0.y;
        s[2] += f1.x; q[2] += f1.x * f1.x;
        s[3] += f1.y; q[3] += f1.y * f1.y;
        s[4] += f2.x; q[4] += f2.x * f2.x;
        s[5] += f2.y; q[5] += f2.y * f2.y;
        s[6] += f3.x; q[6] += f3.x * f3.x;
        s[7] += f3.y; q[7] += f3.y * f3.y;
    }

    __shared__ float sm_s[8][DCOL];
    __shared__ float sm_q[8][DCOL];
#pragma unroll
    for (int j = 0; j < 8; j++) {
        sm_s[rg][lane * 8 + j] = s[j];
        sm_q[rg][lane * 8 + j] = q[j];
    }
    __syncthreads();
    float ss = 0.f, qq = 0.f;
#pragma unroll
    for (int gg2 = 0; gg2 < 8; gg2++) {
        ss += sm_s[gg2][t];
        qq += sm_q[gg2][t];
    }
    atomicAdd(&g_colsum[t], ss);
    atomicAdd(&g_colsq[t], qq);
    __threadfence();

    __shared__ int last;
    if (t == 0) last = (atomicAdd(&g_stats_ctr, 1) == (int)gridDim.x - 1) ? 1 : 0;
    __syncthreads();
    if (last) {
        float inv_n = 1.f / (float)n;
        float mu = g_colsum[t] * inv_n;
        float var = g_colsq[t] * inv_n - mu * mu;
        float rs = rsqrtf(var + 1e-5f);
        float sc = gamma[t] * rs;
        g_sc[layer][t] = sc;
        g_sh[layer][t] = beta[t] - mu * sc;
        g_colsum[t] = 0.f;
        g_colsq[t] = 0.f;
        if (t == 0) g_stats_ctr = 0;
    }
}

// ---------------- pool + readout (lazy act on z2, fp16) ----------------
__global__ void k_pool_out(const __half* __restrict__ z, const int* __restrict__ batch,
                           const float* __restrict__ Wr, const float* __restrict__ br,
                           float* __restrict__ out, int n) {
    int gg = blockIdx.x;
    int t = threadIdx.x;
    int lo = 0, hi = n;
    while (lo < hi) { int m = (lo + hi) >> 1; if (batch[m] < gg) lo = m + 1; else hi = m; }
    int start = lo;
    lo = start; hi = n;
    while (lo < hi) { int m = (lo + hi) >> 1; if (batch[m] < gg + 1) lo = m + 1; else hi = m; }
    int end = lo;

    float sc = g_sc[2][t], sh = g_sh[2][t];
    float sum = 0.f;
    for (int r = start; r < end; ++r)
        sum += elu_act(__half2float(z[(size_t)r * DCOL + t]), sc, sh);
    float cnt = (float)(end - start);
    float v = sum / fmaxf(cnt, 1.f);

    __shared__ float red[DCOL];
    for (int c = 0; c < 2; ++c) {
        red[t] = v * Wr[t * 2 + c];
        __syncthreads();
        for (int s = 128; s > 0; s >>= 1) {
            if (t < s) red[t] += red[t + s];
            __syncthreads();
        }
        if (t == 0) out[gg * 2 + c] = red[0] + br[c];
        __syncthreads();
    }
}

// ---------------- launch ----------------
extern "C" void kernel_launch(void* const* d_in, const int* in_sizes, int n_in,
                              void* d_out, int out_size) {
    const float* x     = (const float*)d_in[0];
    const int*   ei    = (const int*)d_in[1];
    const int*   batch = (const int*)d_in[2];
    const float* W[3]     = { (const float*)d_in[3],  (const float*)d_in[7],  (const float*)d_in[11] };
    const float* b[3]     = { (const float*)d_in[4],  (const float*)d_in[8],  (const float*)d_in[12] };
    const float* gamma[3] = { (const float*)d_in[5],  (const float*)d_in[9],  (const float*)d_in[13] };
    const float* beta[3]  = { (const float*)d_in[6],  (const float*)d_in[10], (const float*)d_in[14] };
    const float* Wr = (const float*)d_in[15];
    const float* br = (const float*)d_in[16];
    float* out = (float*)d_out;

    int n = in_sizes[0] / DCOL;
    int e = in_sizes[1] / 2;
    int g = out_size / 2;
    const int* src = ei;
    const int* dst = ei + e;

    __half2* p_hw;
    __half *p_z0, *p_z1, *p_wh;
    float *p_sc, *p_sh;
    cudaGetSymbolAddress((void**)&p_hw, g_hw);
    cudaGetSymbolAddress((void**)&p_z0, g_z0);
    cudaGetSymbolAddress((void**)&p_z1, g_z1);
    cudaGetSymbolAddress((void**)&p_sc, g_sc);
    cudaGetSymbolAddress((void**)&p_sh, g_sh);
    cudaGetSymbolAddress((void**)&p_wh, g_Wh);

    const int GEMM_SMEM = (2 * 64 * PADK + 2 * 256 * PADK) * 2;
    cudaFuncSetAttribute(k_gemm<0>, cudaFuncAttributeMaxDynamicSharedMemorySize, GEMM_SMEM);
    cudaFuncSetAttribute(k_gemm<1>, cudaFuncAttributeMaxDynamicSharedMemorySize, GEMM_SMEM);

    // ---- preprocessing: 5 launches, single stream ----
    int nb256_e = (e + 255) / 256;
    int nb1024  = (n + 1023) / 1024;
    int nb_fill = (e + n + 255) / 256;

    k_count_deg<<<nb256_e, 256>>>(dst, e);
    k_scan_block<<<nb1024, 1024>>>(n);
    k_scan_sums_prepW<<<1 + 768, 256>>>(nb1024, W[0], W[1], W[2]);
    k_scan_final<<<nb1024, 1024>>>(n);
    k_fill<<<nb_fill, 256>>>(src, dst, e, n);

    int gemm_grid = (n + 63) / 64;
    int nb_agg   = (n + 7) / 8;
    int nb_stats = (n + 127) / 128;

    // ---- layer 0: A=x raw (fp32), prev=none -> z0 ----
    k_gemm<0><<<gemm_grid, 256, GEMM_SMEM>>>(x, p_wh + 0 * 65536, p_hw, n, nullptr, nullptr);
    k_agg<<<nb_agg, 256>>>((const uint4*)p_hw, nullptr, nullptr, nullptr, nullptr,
                           (const float4*)b[0], (uint4*)p_z0, n);
    k_stats<<<nb_stats, 256>>>(p_z0, gamma[0], beta[0], n, 0);

    // ---- layer 1: A=act0(z0) fp16, prev=x fp32 -> z1 ----
    k_gemm<1><<<gemm_grid, 256, GEMM_SMEM>>>(p_z0, p_wh + 1 * 65536, p_hw, n,
                                             p_sc + 0 * DCOL, p_sh + 0 * DCOL);
    k_agg<<<nb_agg, 256>>>((const uint4*)p_hw, (const float4*)x, nullptr, nullptr, nullptr,
                           (const float4*)b[1], (uint4*)p_z1, n);
    k_stats<<<nb_stats, 256>>>(p_z1, gamma[1], beta[1], n, 1);

    // ---- layer 2: A=act1(z1) fp16, prev=act0(z0) fp16 -> z2 (overwrites z0) ----
    k_gemm<1><<<gemm_grid, 256, GEMM_SMEM>>>(p_z1, p_wh + 2 * 65536, p_hw, n,
                                             p_sc + 1 * DCOL, p_sh + 1 * DCOL);
    k_agg<<<nb_agg, 256>>>((const uint4*)p_hw, nullptr, p_z0,
                           p_sc + 0 * DCOL, p_sh + 0 * DCOL,
                           (const float4*)b[2], (uint4*)p_z0, n);
    k_stats<<<nb_stats, 256>>>(p_z0, gamma[2], beta[2], n, 2);

    // ---- pool + readout (act2 lazy) ----
    k_pool_out<<<g, 256>>>(p_z0, batch, Wr, br, out, n);
}

// round 16
// speedup vs baseline: 1.0827x; 1.0198x over previous
#include <cuda_runtime.h>
#include <cuda_fp16.h>
#include <cstdint>
#include <math.h>

#define MAXN 65536
#define MAXE (1 << 21)
#define DCOL 256

// ---------------- static device scratch ----------------
__device__ __half2 g_hw[MAXN * (DCOL / 2)];  // (h @ W) * dinv[row], fp16
__device__ __half g_z0[MAXN * DCOL];  // z0 / z2 (pre-BN), fp16
__device__ __half g_z1[MAXN * DCOL];  // z1 (pre-BN), fp16
__device__ int   g_deg[MAXN];         // starts 0; re-zeroed by k_agg each call
__device__ int   g_scan[MAXN];
__device__ int   g_rowptr[MAXN + 1];
__device__ int   g_cursor[MAXN];
__device__ int   g_csr[MAXE];
__device__ int   g_bsums[128];
__device__ float g_dinv[MAXN];
__device__ float g_colsum[DCOL];      // starts 0; zeroed by stats last-block
__device__ float g_colsq[DCOL];
__device__ int   g_stats_ctr;         // starts 0; reset by stats last-block
__device__ float g_sc[3][DCOL];
__device__ float g_sh[3][DCOL];
__device__ __half g_Wh[3][DCOL * DCOL];   // W fp16, transposed [n][k]

__device__ __forceinline__ float elu_act(float z, float sc, float sh) {
    float v = fmaf(z, sc, sh);
    return v > 0.f ? v : expm1f(v);
}

__device__ __forceinline__ void mma16816(float* d, const uint32_t* a, const uint32_t* b) {
    asm volatile(
        "mma.sync.aligned.m16n8k16.row.col.f32.f16.f16.f32 "
        "{%0,%1,%2,%3},{%4,%5,%6,%7},{%8,%9},{%0,%1,%2,%3};"
        : "+f"(d[0]), "+f"(d[1]), "+f"(d[2]), "+f"(d[3])
        : "r"(a[0]), "r"(a[1]), "r"(a[2]), "r"(a[3]), "r"(b[0]), "r"(b[1]));
}

__device__ __forceinline__ void ldsm_x4(uint32_t* r, uint32_t saddr) {
    asm volatile("ldmatrix.sync.aligned.m8n8.x4.shared.b16 {%0,%1,%2,%3}, [%4];"
                 : "=r"(r[0]), "=r"(r[1]), "=r"(r[2]), "=r"(r[3]) : "r"(saddr));
}

__device__ __forceinline__ void cp_async16(uint32_t saddr, const void* gptr) {
    asm volatile("cp.async.cg.shared.global [%0], [%1], 16;" :: "r"(saddr), "l"(gptr));
}

// accumulate 8 halves (packed in uint4) into float[8]
__device__ __forceinline__ void acc8(float* a, uint4 u) {
    __half2* h = (__half2*)&u;
    float2 f0 = __half22float2(h[0]);
    float2 f1 = __half22float2(h[1]);
    float2 f2 = __half22float2(h[2]);
    float2 f3 = __half22float2(h[3]);
    a[0] += f0.x; a[1] += f0.y; a[2] += f1.x; a[3] += f1.y;
    a[4] += f2.x; a[5] += f2.y; a[6] += f3.x; a[7] += f3.y;
}

// ---------------- preprocessing ----------------
__global__ void k_prepW(const float* __restrict__ W0, const float* __restrict__ W1,
                        const float* __restrict__ W2) {
    int idx = blockIdx.x * 256 + threadIdx.x;   // 0 .. 3*65536-1
    int layer = idx >> 16;
    int rem = idx & 65535;           // rem = k*256 + n
    int k = rem >> 8;
    int nn = rem & 255;
    const float* Ws = (layer == 0) ? W0 : (layer == 1) ? W1 : W2;
    g_Wh[layer][nn * 256 + k] = __float2half_rn(Ws[rem]);
}

__global__ void k_count_deg(const int* __restrict__ dst, int e) {
    int i = blockIdx.x * blockDim.x + threadIdx.x;
    if (i < e) atomicAdd(&g_deg[dst[i]], 1);
}

__global__ void k_scan_block(int n) {
    __shared__ int sh[1024];
    int i = blockIdx.x * 1024 + threadIdx.x;
    int v = 0;
    if (i < n) {
        v = g_deg[i] + 1;          // + self loop
        g_deg[i] = v;
        g_dinv[i] = rsqrtf((float)v);
    }
    sh[threadIdx.x] = v;
    __syncthreads();
    for (int off = 1; off < 1024; off <<= 1) {
        int t = (threadIdx.x >= off) ? sh[threadIdx.x - off] : 0;
        __syncthreads();
        sh[threadIdx.x] += t;
        __syncthreads();
    }
    if (i < n) g_scan[i] = sh[threadIdx.x];
    if (threadIdx.x == 1023) g_bsums[blockIdx.x] = sh[1023];
}

// parallel Hillis-Steele scan of block sums (nb <= 128)
__global__ void k_scan_sums(int nb) {
    __shared__ int sh[128];
    int t = threadIdx.x;
    int v = (t < nb) ? g_bsums[t] : 0;
    sh[t] = v;
    __syncthreads();
    for (int off = 1; off < 128; off <<= 1) {
        int u = (t >= off) ? sh[t - off] : 0;
        __syncthreads();
        sh[t] += u;
        __syncthreads();
    }
    if (t < nb) g_bsums[t] = sh[t];
}

__global__ void k_scan_final(int n) {
    int i = blockIdx.x * 1024 + threadIdx.x;
    if (i < n) {
        int off = (blockIdx.x > 0) ? g_bsums[blockIdx.x - 1] : 0;
        int incl = g_scan[i] + off;
        g_rowptr[i + 1] = incl;
        g_cursor[i] = incl - g_deg[i];
        if (i == 0) g_rowptr[0] = 0;
    }
}

__global__ void k_fill(const int* __restrict__ src, const int* __restrict__ dst, int e, int n) {
    int i = blockIdx.x * blockDim.x + threadIdx.x;
    if (i < e) {
        int d = dst[i];
        int p = atomicAdd(&g_cursor[d], 1);
        g_csr[p] = src[i];
    } else if (i - e < n) {
        int j = i - e;
        int p = atomicAdd(&g_cursor[j], 1);
        g_csr[p] = j;
    }
}

// ---------------- pipelined fp16 tensor-core GEMM ----------------
// Chw[r][c] = fp16( (act(A) @ W)[r][c] * dinv[r] ).
// MODE 0: A fp32 row-major, no activation (layer 0, A = x).
// MODE 1: A fp16 row-major (z), lazy BN+ELU applied via scl/sft.
// BM=64, BN=256, BK=32, 256 threads = 8 warps (2m x 4n), warp tile 32x64.
#define PADK 40
template <int MODE>
__global__ __launch_bounds__(256, 2)
void k_gemm(const void* __restrict__ Av,
            const __half* __restrict__ Wh,
            __half2* __restrict__ C, int M,
            const float* __restrict__ scl, const float* __restrict__ sft) {
    extern __shared__ __half sm[];
    __half* Ah = sm;                              // 2 stages * 64 * PADK
    __half* Bh = Ah + 2 * 64 * PADK;              // 2 stages * 256 * PADK

    uint32_t sAh = (uint32_t)__cvta_generic_to_shared(Ah);
    uint32_t sBh = (uint32_t)__cvta_generic_to_shared(Bh);

    int tid = threadIdx.x;
    int brow = blockIdx.x * 64;
    int lane = tid & 31;
    int warp = tid >> 5;
    int wm = warp & 1;
    int wn = warp >> 1;
    int g  = lane >> 2;
    int tg = lane & 3;

    int aRow = tid >> 2;
    int aCb  = (tid & 3) * 8;
    int gRow = brow + aRow;
    const float*  ApF = (const float*)Av  + (size_t)gRow * 256 + aCb;
    const __half* ApH = (const __half*)Av + (size_t)gRow * 256 + aCb;

    int bRow0 = tid >> 2;
    int bChunk = (tid & 3) * 8;

    int lmRow = lane & 15;
    int lmCol = (lane >> 4) * 8;

    float acc[2][8][4];
#pragma unroll
    for (int mt = 0; mt < 2; mt++)
#pragma unroll
        for (int nt = 0; nt < 8; nt++)
#pragma unroll
            for (int j = 0; j < 4; j++) acc[mt][nt][j] = 0.f;

    auto loadA = [&](int kt, float4& v0, float4& v1) {
        if (MODE == 0) {
            if (gRow < M) {
                v0 = *(const float4*)(ApF + kt);
                v1 = *(const float4*)(ApF + kt + 4);
            } else {
                v0 = make_float4(0.f, 0.f, 0.f, 0.f);
                v1 = make_float4(0.f, 0.f, 0.f, 0.f);
            }
        } else {
            uint4 u = make_uint4(0, 0, 0, 0);
            if (gRow < M) u = *(const uint4*)(ApH + kt);
            __half2* hp = (__half2*)&u;
            float2 f0 = __half22float2(hp[0]);
            float2 f1 = __half22float2(hp[1]);
            float2 f2 = __half22float2(hp[2]);
            float2 f3 = __half22float2(hp[3]);
            int c = kt + aCb;
            v0.x = elu_act(f0.x, scl[c + 0], sft[c + 0]);
            v0.y = elu_act(f0.y, scl[c + 1], sft[c + 1]);
            v0.z = elu_act(f1.x, scl[c + 2], sft[c + 2]);
            v0.w = elu_act(f1.y, scl[c + 3], sft[c + 3]);
            v1.x = elu_act(f2.x, scl[c + 4], sft[c + 4]);
            v1.y = elu_act(f2.y, scl[c + 5], sft[c + 5]);
            v1.z = elu_act(f3.x, scl[c + 6], sft[c + 6]);
            v1.w = elu_act(f3.y, scl[c + 7], sft[c + 7]);
        }
    };
    auto storeA = [&](int stage, float4 v0, float4 v1) {
        __half* ah = Ah + stage * 64 * PADK + aRow * PADK + aCb;
        *(__half2*)(ah + 0) = __floats2half2_rn(v0.x, v0.y);
        *(__half2*)(ah + 2) = __floats2half2_rn(v0.z, v0.w);
        *(__half2*)(ah + 4) = __floats2half2_rn(v1.x, v1.y);
        *(__half2*)(ah + 6) = __floats2half2_rn(v1.z, v1.w);
    };
    auto asyncB = [&](int stage, int kt) {
#pragma unroll
        for (int rep = 0; rep < 4; rep++) {
            int row = bRow0 + rep * 64;
            uint32_t soff = (uint32_t)((stage * 256 + row) * PADK + bChunk) * 2;
            const __half* gh = Wh + (size_t)row * 256 + kt + bChunk;
            cp_async16(sBh + soff, gh);
        }
    };
    auto compute = [&](int stage) {
#pragma unroll
        for (int ks = 0; ks < 2; ks++) {
            int k0 = ks * 16;
            uint32_t ah[2][4];
#pragma unroll
            for (int mt = 0; mt < 2; mt++) {
                int m = wm * 32 + mt * 16 + lmRow;
                uint32_t off = (uint32_t)((stage * 64 + m) * PADK + k0 + lmCol) * 2;
                ldsm_x4(ah[mt], sAh + off);
            }
#pragma unroll
            for (int pair = 0; pair < 4; pair++) {
                int n0 = wn * 64 + pair * 16 + lmRow;
                uint32_t off = (uint32_t)((stage * 256 + n0) * PADK + k0 + lmCol) * 2;
                uint32_t bhr[4];
                ldsm_x4(bhr, sBh + off);
                uint32_t b_ev[2] = {bhr[0], bhr[2]};
                uint32_t b_od[2] = {bhr[1], bhr[3]};
                int nt0 = pair * 2;
#pragma unroll
                for (int mt = 0; mt < 2; mt++) {
                    mma16816(acc[mt][nt0], ah[mt], b_ev);
                    mma16816(acc[mt][nt0 + 1], ah[mt], b_od);
                }
            }
        }
    };

    {
        asyncB(0, 0);
        float4 v0, v1;
        loadA(0, v0, v1);
        storeA(0, v0, v1);
        asm volatile("cp.async.commit_group;");
        asm volatile("cp.async.wait_group 0;");
        __syncthreads();
    }

#pragma unroll
    for (int it = 0; it < 8; ++it) {
        int cur = it & 1;
        float4 v0, v1;
        if (it < 7) {
            asyncB(cur ^ 1, (it + 1) * 32);
            loadA((it + 1) * 32, v0, v1);
        }
        asm volatile("cp.async.commit_group;");
        compute(cur);
        if (it < 7) storeA(cur ^ 1, v0, v1);
        asm volatile("cp.async.wait_group 0;");
        __syncthreads();
    }

#pragma unroll
    for (int mt = 0; mt < 2; mt++) {
        int r0 = brow + wm * 32 + mt * 16 + g;
        int r1 = r0 + 8;
        float s0 = (r0 < M) ? g_dinv[r0] : 0.f;
        float s1 = (r1 < M) ? g_dinv[r1] : 0.f;
#pragma unroll
        for (int nt = 0; nt < 8; nt++) {
            int col = wn * 64 + nt * 8 + tg * 2;
            if (r0 < M)
                C[(size_t)r0 * 128 + (col >> 1)] =
                    __floats2half2_rn(acc[mt][nt][0] * s0, acc[mt][nt][1] * s0);
            if (r1 < M)
                C[(size_t)r1 * 128 + (col >> 1)] =
                    __floats2half2_rn(acc[mt][nt][2] * s1, acc[mt][nt][3] * s1);
        }
    }
}

// ---------------- aggregation: 8 rows/block, 32 lanes x 16B per row (R13) ----------------
__global__ void k_agg(const uint4* __restrict__ hws,   // row stride 32 uint4
                      const float4* __restrict__ prev_f, const __half* __restrict__ prev_h,
                      const float* __restrict__ pscl, const float* __restrict__ psft,
                      const float4* __restrict__ bias, uint4* __restrict__ z, int n) {
    int row = blockIdx.x * 8 + (threadIdx.x >> 5);
    if (row >= n) return;
    int lane = threadIdx.x & 31;
    if (lane == 0) g_deg[row] = 0;   // reset for next graph replay
    int s0 = g_rowptr[row], s1 = g_rowptr[row + 1];

    float a0[8] = {0.f, 0.f, 0.f, 0.f, 0.f, 0.f, 0.f, 0.f};
    float a1[8] = {0.f, 0.f, 0.f, 0.f, 0.f, 0.f, 0.f, 0.f};

    int e = s0;
    for (; e + 3 < s1; e += 4) {
        int sa = g_csr[e + 0];
        int sb = g_csr[e + 1];
        int sc = g_csr[e + 2];
        int sd = g_csr[e + 3];
        uint4 ua = hws[(size_t)sa * 32 + lane];
        uint4 ub = hws[(size_t)sb * 32 + lane];
        uint4 uc = hws[(size_t)sc * 32 + lane];
        uint4 ud = hws[(size_t)sd * 32 + lane];
        acc8(a0, ua);
        acc8(a1, ub);
        acc8(a0, uc);
        acc8(a1, ud);
    }
    for (; e < s1; ++e) {
        int sa = g_csr[e];
        acc8(a0, hws[(size_t)sa * 32 + lane]);
    }
#pragma unroll
    for (int j = 0; j < 8; j++) a0[j] += a1[j];

    float d = g_dinv[row];
    float4 b0 = bias[lane * 2];
    float4 b1 = bias[lane * 2 + 1];
    float o[8];
    o[0] = fmaf(d, a0[0], b0.x);
    o[1] = fmaf(d, a0[1], b0.y);
    o[2] = fmaf(d, a0[2], b0.z);
    o[3] = fmaf(d, a0[3], b0.w);
    o[4] = fmaf(d, a0[4], b1.x);
    o[5] = fmaf(d, a0[5], b1.y);
    o[6] = fmaf(d, a0[6], b1.z);
    o[7] = fmaf(d, a0[7], b1.w);

    if (prev_f) {
        float4 p0 = prev_f[(size_t)row * 64 + lane * 2];
        float4 p1 = prev_f[(size_t)row * 64 + lane * 2 + 1];
        o[0] += p0.x; o[1] += p0.y; o[2] += p0.z; o[3] += p0.w;
        o[4] += p1.x; o[5] += p1.y; o[6] += p1.z; o[7] += p1.w;
    } else if (prev_h) {
        uint4 ph = ((const uint4*)prev_h)[(size_t)row * 32 + lane];
        __half2* hp = (__half2*)&ph;
        float pf[8];
        float2 f0 = __half22float2(hp[0]);
        float2 f1 = __half22float2(hp[1]);
        float2 f2 = __half22float2(hp[2]);
        float2 f3 = __half22float2(hp[3]);
        pf[0] = f0.x; pf[1] = f0.y; pf[2] = f1.x; pf[3] = f1.y;
        pf[4] = f2.x; pf[5] = f2.y; pf[6] = f3.x; pf[7] = f3.y;
        int c = lane * 8;
#pragma unroll
        for (int j = 0; j < 8; j++) o[j] += elu_act(pf[j], pscl[c + j], psft[c + j]);
    }

    __half2 h0 = __floats2half2_rn(o[0], o[1]);
    __half2 h1 = __floats2half2_rn(o[2], o[3]);
    __half2 h2 = __floats2half2_rn(o[4], o[5]);
    __half2 h3 = __floats2half2_rn(o[6], o[7]);
    uint4 pk;
    pk.x = *(uint32_t*)&h0;
    pk.y = *(uint32_t*)&h1;
    pk.z = *(uint32_t*)&h2;
    pk.w = *(uint32_t*)&h3;
    z[(size_t)row * 32 + lane] = pk;
}

// ---------------- batchnorm stats (vectorized uint4 reads) + fused finalize ----------------
__global__ void k_stats(const __half* __restrict__ z,
                        const float* __restrict__ gamma, const float* __restrict__ beta,
                        int n, int layer) {
    int t = threadIdx.x;
    int lane = t & 31;      // column group: cols lane*8 .. lane*8+7
    int rg = t >> 5;        // row-group 0..7
    int r0 = blockIdx.x * 128;

    float s[8] = {0.f, 0.f, 0.f, 0.f, 0.f, 0.f, 0.f, 0.f};
    float q[8] = {0.f, 0.f, 0.f, 0.f, 0.f, 0.f, 0.f, 0.f};

    const uint4* z4 = (const uint4*)z;   // row stride 32 uint4
    for (int r = r0 + rg; r < min(n, r0 + 128); r += 8) {
        uint4 u = z4[(size_t)r * 32 + lane];
        __half2* h = (__half2*)&u;
        float2 f0 = __half22float2(h[0]);
        float2 f1 = __half22float2(h[1]);
        float2 f2 = __half22float2(h[2]);
        float2 f3 = __half22float2(h[3]);
        s[0] += f0.x; q[0] += f0.x * f0.x;
        s[1] += f0.y; q[1] += f0.y * f0.y;
        s[2] += f1.x; q[2] += f1.x * f1.x;
        s[3] += f1.y; q[3] += f1.y * f1.y;
        s[4] += f2.x; q[4] += f2.x * f2.x;
        s[5] += f2.y; q[5] += f2.y * f2.y;
        s[6] += f3.x; q[6] += f3.x * f3.x;
        s[7] += f3.y; q[7] += f3.y * f3.y;
    }

    __shared__ float sm_s[8][DCOL];
    __shared__ float sm_q[8][DCOL];
#pragma unroll
    for (int j = 0; j < 8; j++) {
        sm_s[rg][lane * 8 + j] = s[j];
        sm_q[rg][lane * 8 + j] = q[j];
    }
    __syncthreads();
    float ss = 0.f, qq = 0.f;
#pragma unroll
    for (int gg2 = 0; gg2 < 8; gg2++) {
        ss += sm_s[gg2][t];
        qq += sm_q[gg2][t];
    }
    atomicAdd(&g_colsum[t], ss);
    atomicAdd(&g_colsq[t], qq);
    __threadfence();

    __shared__ int last;
    if (t == 0) last = (atomicAdd(&g_stats_ctr, 1) == (int)gridDim.x - 1) ? 1 : 0;
    __syncthreads();
    if (last) {
        float inv_n = 1.f / (float)n;
        float mu = g_colsum[t] * inv_n;
        float var = g_colsq[t] * inv_n - mu * mu;
        float rs = rsqrtf(var + 1e-5f);
        float sc = gamma[t] * rs;
        g_sc[layer][t] = sc;
        g_sh[layer][t] = beta[t] - mu * sc;
        g_colsum[t] = 0.f;
        g_colsq[t] = 0.f;
        if (t == 0) g_stats_ctr = 0;
    }
}

// ---------------- pool + readout (lazy act on z2, fp16) ----------------
__global__ void k_pool_out(const __half* __restrict__ z, const int* __restrict__ batch,
                           const float* __restrict__ Wr, const float* __restrict__ br,
                           float* __restrict__ out, int n) {
    int gg = blockIdx.x;
    int t = threadIdx.x;
    int lo = 0, hi = n;
    while (lo < hi) { int m = (lo + hi) >> 1; if (batch[m] < gg) lo = m + 1; else hi = m; }
    int start = lo;
    lo = start; hi = n;
    while (lo < hi) { int m = (lo + hi) >> 1; if (batch[m] < gg + 1) lo = m + 1; else hi = m; }
    int end = lo;

    float sc = g_sc[2][t], sh = g_sh[2][t];
    float sum = 0.f;
    for (int r = start; r < end; ++r)
        sum += elu_act(__half2float(z[(size_t)r * DCOL + t]), sc, sh);
    float cnt = (float)(end - start);
    float v = sum / fmaxf(cnt, 1.f);

    __shared__ float red[DCOL];
    for (int c = 0; c < 2; ++c) {
        red[t] = v * Wr[t * 2 + c];
        __syncthreads();
        for (int s = 128; s > 0; s >>= 1) {
            if (t < s) red[t] += red[t + s];
            __syncthreads();
        }
        if (t == 0) out[gg * 2 + c] = red[0] + br[c];
        __syncthreads();
    }
}

// ---------------- launch ----------------
extern "C" void kernel_launch(void* const* d_in, const int* in_sizes, int n_in,
                              void* d_out, int out_size) {
    const float* x     = (const float*)d_in[0];
    const int*   ei    = (const int*)d_in[1];
    const int*   batch = (const int*)d_in[2];
    const float* W[3]     = { (const float*)d_in[3],  (const float*)d_in[7],  (const float*)d_in[11] };
    const float* b[3]     = { (const float*)d_in[4],  (const float*)d_in[8],  (const float*)d_in[12] };
    const float* gamma[3] = { (const float*)d_in[5],  (const float*)d_in[9],  (const float*)d_in[13] };
    const float* beta[3]  = { (const float*)d_in[6],  (const float*)d_in[10], (const float*)d_in[14] };
    const float* Wr = (const float*)d_in[15];
    const float* br = (const float*)d_in[16];
    float* out = (float*)d_out;

    int n = in_sizes[0] / DCOL;
    int e = in_sizes[1] / 2;
    int g = out_size / 2;
    const int* src = ei;
    const int* dst = ei + e;

    __half2* p_hw;
    __half *p_z0, *p_z1, *p_wh;
    float *p_sc, *p_sh;
    cudaGetSymbolAddress((void**)&p_hw, g_hw);
    cudaGetSymbolAddress((void**)&p_z0, g_z0);
    cudaGetSymbolAddress((void**)&p_z1, g_z1);
    cudaGetSymbolAddress((void**)&p_sc, g_sc);
    cudaGetSymbolAddress((void**)&p_sh, g_sh);
    cudaGetSymbolAddress((void**)&p_wh, g_Wh);

    const int GEMM_SMEM = (2 * 64 * PADK + 2 * 256 * PADK) * 2;
    cudaFuncSetAttribute(k_gemm<0>, cudaFuncAttributeMaxDynamicSharedMemorySize, GEMM_SMEM);
    cudaFuncSetAttribute(k_gemm<1>, cudaFuncAttributeMaxDynamicSharedMemorySize, GEMM_SMEM);

    // lazily-created side stream + events (host objects; created on the
    // uncaptured correctness call, reused during graph capture)
    static cudaStream_t s2 = nullptr;
    static cudaEvent_t evA = nullptr, evB = nullptr;
    if (!s2) {
        cudaStreamCreateWithFlags(&s2, cudaStreamNonBlocking);
        cudaEventCreateWithFlags(&evA, cudaEventDisableTiming);
        cudaEventCreateWithFlags(&evB, cudaEventDisableTiming);
    }

    int nb256_e = (e + 255) / 256;
    int nb1024  = (n + 1023) / 1024;
    int nb_fill = (e + n + 255) / 256;
    int gemm_grid = (n + 63) / 64;
    int nb_agg   = (n + 7) / 8;
    int nb_stats = (n + 127) / 128;

    // ---- preprocessing with gemm0 forked onto side stream ----
    k_prepW<<<768, 256>>>(W[0], W[1], W[2]);
    k_count_deg<<<nb256_e, 256>>>(dst, e);
    k_scan_block<<<nb1024, 1024>>>(n);          // writes g_dinv

    cudaEventRecord(evA, 0);
    cudaStreamWaitEvent(s2, evA, 0);
    k_gemm<0><<<gemm_grid, 256, GEMM_SMEM, s2>>>(x, p_wh + 0 * 65536, p_hw, n, nullptr, nullptr);
    cudaEventRecord(evB, s2);

    k_scan_sums<<<1, 128>>>(nb1024);
    k_scan_final<<<nb1024, 1024>>>(n);
    k_fill<<<nb_fill, 256>>>(src, dst, e, n);

    cudaStreamWaitEvent(0, evB, 0);             // join before agg0

    // ---- layer 0: prev=none -> z0 ----
    k_agg<<<nb_agg, 256>>>((const uint4*)p_hw, nullptr, nullptr, nullptr, nullptr,
                           (const float4*)b[0], (uint4*)p_z0, n);
    k_stats<<<nb_stats, 256>>>(p_z0, gamma[0], beta[0], n, 0);

    // ---- layer 1: A=act0(z0) fp16, prev=x fp32 -> z1 ----
    k_gemm<1><<<gemm_grid, 256, GEMM_SMEM>>>(p_z0, p_wh + 1 * 65536, p_hw, n,
                                             p_sc + 0 * DCOL, p_sh + 0 * DCOL);
    k_agg<<<nb_agg, 256>>>((const uint4*)p_hw, (const float4*)x, nullptr, nullptr, nullptr,
                           (const float4*)b[1], (uint4*)p_z1, n);
    k_stats<<<nb_stats, 256>>>(p_z1, gamma[1], beta[1], n, 1);

    // ---- layer 2: A=act1(z1) fp16, prev=act0(z0) fp16 -> z2 (overwrites z0) ----
    k_gemm<1><<<gemm_grid, 256, GEMM_SMEM>>>(p_z1, p_wh + 2 * 65536, p_hw, n,
                                             p_sc + 1 * DCOL, p_sh + 1 * DCOL);
    k_agg<<<nb_agg, 256>>>((const uint4*)p_hw, nullptr, p_z0,
                           p_sc + 0 * DCOL, p_sh + 0 * DCOL,
                           (const float4*)b[2], (uint4*)p_z0, n);
    k_stats<<<nb_stats, 256>>>(p_z0, gamma[2], beta[2], n, 2);

    // ---- pool + readout (act2 lazy) ----
    k_pool_out<<<g, 256>>>(p_z0, batch, Wr, br, out, n);
}